// round 1
// baseline (speedup 1.0000x reference)
#include <cuda_runtime.h>

#define TT  30
#define TD  150
#define DIM 512
#define NEGF (-1e30f)

__global__ __launch_bounds__(128, 8)
void swem_cat_kernel(const void* __restrict__ title_v,
                     const void* __restrict__ desc_v,
                     const void* __restrict__ tlen_v,
                     const void* __restrict__ dlen_v,
                     const float* __restrict__ w2v,
                     float* __restrict__ out)
{
    __shared__ int s_idx[TT + TD];
    __shared__ int s_len[2];
    __shared__ int s_is64;

    const int b   = blockIdx.x;
    const int tid = threadIdx.x;

    // ---- dtype detection: int64 vs int32 indices -------------------------
    // If indices are int64 (little-endian), the high 32-bit word of each
    // element is 0 (values are in [0, 34835]). Check the first 32 elements
    // of the global title array; false-positive prob ~ (1/34836)^32 ~ 0.
    if (tid < 32) {
        unsigned hi  = ((const unsigned*)title_v)[2 * tid + 1];
        unsigned any = __ballot_sync(0xffffffffu, hi != 0u);
        if (tid == 0) s_is64 = (any == 0u) ? 1 : 0;
    }
    __syncthreads();

    // ---- stage indices + lengths into shared -----------------------------
    if (s_is64) {
        const long long* tp = (const long long*)title_v + (long long)b * TT;
        const long long* dp = (const long long*)desc_v  + (long long)b * TD;
        if (tid < TT) s_idx[tid] = (int)tp[tid];
        for (int i = tid; i < TD; i += 128) s_idx[TT + i] = (int)dp[i];
        if (tid == 0) {
            s_len[0] = (int)((const long long*)tlen_v)[b];
            s_len[1] = (int)((const long long*)dlen_v)[b];
        }
    } else {
        const int* tp = (const int*)title_v + b * TT;
        const int* dp = (const int*)desc_v  + b * TD;
        if (tid < TT) s_idx[tid] = tp[tid];
        for (int i = tid; i < TD; i += 128) s_idx[TT + i] = dp[i];
        if (tid == 0) {
            s_len[0] = ((const int*)tlen_v)[b];
            s_len[1] = ((const int*)dlen_v)[b];
        }
    }
    __syncthreads();

    const int tl = s_len[0];
    const int dl = s_len[1];
    const int d4 = tid * 4;                       // 128 threads * 4 = 512 dims
    float* orow = out + (size_t)b * (4 * DIM);

    // ---- title pool -------------------------------------------------------
    {
        float4 mx = make_float4(NEGF, NEGF, NEGF, NEGF);
        float4 sm = make_float4(0.f, 0.f, 0.f, 0.f);
        #pragma unroll 4
        for (int t = 0; t < tl; t++) {
            const float4 v = *(const float4*)(w2v + (size_t)s_idx[t] * DIM + d4);
            mx.x = fmaxf(mx.x, v.x); mx.y = fmaxf(mx.y, v.y);
            mx.z = fmaxf(mx.z, v.z); mx.w = fmaxf(mx.w, v.w);
            sm.x += v.x; sm.y += v.y; sm.z += v.z; sm.w += v.w;
        }
        const float inv = 1.0f / (float)(tl > 1 ? tl : 1);
        float4 av;
        if (tl > 0) {
            av = make_float4(sm.x * inv, sm.y * inv, sm.z * inv, sm.w * inv);
        } else {
            mx = make_float4(0.f, 0.f, 0.f, 0.f);
            av = make_float4(0.f, 0.f, 0.f, 0.f);
        }
        *(float4*)(orow + d4)           = mx;   // t_max  -> [0, 512)
        *(float4*)(orow + 2 * DIM + d4) = av;   // t_avg  -> [1024, 1536)
    }

    // ---- desc pool ----------------------------------------------------------
    {
        float4 mx = make_float4(NEGF, NEGF, NEGF, NEGF);
        float4 sm = make_float4(0.f, 0.f, 0.f, 0.f);
        #pragma unroll 4
        for (int t = 0; t < dl; t++) {
            const float4 v = *(const float4*)(w2v + (size_t)s_idx[TT + t] * DIM + d4);
            mx.x = fmaxf(mx.x, v.x); mx.y = fmaxf(mx.y, v.y);
            mx.z = fmaxf(mx.z, v.z); mx.w = fmaxf(mx.w, v.w);
            sm.x += v.x; sm.y += v.y; sm.z += v.z; sm.w += v.w;
        }
        const float inv = 1.0f / (float)(dl > 1 ? dl : 1);
        float4 av;
        if (dl > 0) {
            av = make_float4(sm.x * inv, sm.y * inv, sm.z * inv, sm.w * inv);
        } else {
            mx = make_float4(0.f, 0.f, 0.f, 0.f);
            av = make_float4(0.f, 0.f, 0.f, 0.f);
        }
        *(float4*)(orow + DIM + d4)     = mx;   // d_max  -> [512, 1024)
        *(float4*)(orow + 3 * DIM + d4) = av;   // d_avg  -> [1536, 2048)
    }
}

extern "C" void kernel_launch(void* const* d_in, const int* in_sizes, int n_in,
                              void* d_out, int out_size)
{
    const void* title = d_in[0];
    const void* desc  = d_in[1];
    const void* tlen  = d_in[2];
    const void* dlen  = d_in[3];
    // word2vec is the LAST input (robust to whether 'mode' scalar is passed)
    const float* w2v  = (const float*)d_in[n_in - 1];
    float* out        = (float*)d_out;

    const int B = in_sizes[2];   // t_len has B elements

    swem_cat_kernel<<<B, 128>>>(title, desc, tlen, dlen, w2v, out);
}

// round 2
// speedup vs baseline: 1.0146x; 1.0146x over previous
#include <cuda_runtime.h>

#define TT  30
#define TD  150
#define DIM 512
#define NEGF (-1e30f)

__global__ __launch_bounds__(128, 8)
void swem_cat_kernel(const void* __restrict__ title_v,
                     const void* __restrict__ desc_v,
                     const void* __restrict__ tlen_v,
                     const void* __restrict__ dlen_v,
                     const float* __restrict__ w2v,
                     float* __restrict__ out)
{
    __shared__ int s_idx[TT + TD];
    __shared__ int s_len[2];
    __shared__ int s_is64;

    const int b   = blockIdx.x;
    const int tid = threadIdx.x;

    // ---- dtype detection: int64 vs int32 indices -------------------------
    // int64 little-endian => high 32-bit word of each element is 0
    // (values in [0, 34835]). FP prob ~ (1/34836)^32 ~ 0.
    if (tid < 32) {
        unsigned hi  = ((const unsigned*)title_v)[2 * tid + 1];
        unsigned any = __ballot_sync(0xffffffffu, hi != 0u);
        if (tid == 0) s_is64 = (any == 0u) ? 1 : 0;
    }
    __syncthreads();

    // ---- stage indices + lengths into shared -----------------------------
    if (s_is64) {
        const long long* tp = (const long long*)title_v + (long long)b * TT;
        const long long* dp = (const long long*)desc_v  + (long long)b * TD;
        if (tid < TT) s_idx[tid] = (int)tp[tid];
        for (int i = tid; i < TD; i += 128) s_idx[TT + i] = (int)dp[i];
        if (tid == 0) {
            s_len[0] = (int)((const long long*)tlen_v)[b];
            s_len[1] = (int)((const long long*)dlen_v)[b];
        }
    } else {
        const int* tp = (const int*)title_v + b * TT;
        const int* dp = (const int*)desc_v  + b * TD;
        if (tid < TT) s_idx[tid] = tp[tid];
        for (int i = tid; i < TD; i += 128) s_idx[TT + i] = dp[i];
        if (tid == 0) {
            s_len[0] = ((const int*)tlen_v)[b];
            s_len[1] = ((const int*)dlen_v)[b];
        }
    }
    __syncthreads();

    const int tl = s_len[0];
    const int dl = s_len[1];
    const float* wbase = w2v + tid * 4;     // per-thread dim slice base
    float* orow = out + (size_t)b * (4 * DIM) + tid * 4;

    // ---- title pool (<=30 tokens) -----------------------------------------
    {
        float4 mx = make_float4(NEGF, NEGF, NEGF, NEGF);
        float4 sm = make_float4(0.f, 0.f, 0.f, 0.f);
        #pragma unroll 4
        for (int t = 0; t < tl; t++) {
            const float4 v = *(const float4*)(wbase + (size_t)s_idx[t] * DIM);
            mx.x = fmaxf(mx.x, v.x); mx.y = fmaxf(mx.y, v.y);
            mx.z = fmaxf(mx.z, v.z); mx.w = fmaxf(mx.w, v.w);
            sm.x += v.x; sm.y += v.y; sm.z += v.z; sm.w += v.w;
        }
        float4 av;
        if (tl > 0) {
            const float inv = 1.0f / (float)tl;
            av = make_float4(sm.x * inv, sm.y * inv, sm.z * inv, sm.w * inv);
        } else {
            mx = make_float4(0.f, 0.f, 0.f, 0.f);
            av = make_float4(0.f, 0.f, 0.f, 0.f);
        }
        *(float4*)(orow)           = mx;   // t_max  -> [0, 512)
        *(float4*)(orow + 2 * DIM) = av;   // t_avg  -> [1024, 1536)
    }

    // ---- desc pool (<=150 tokens, dominant) --------------------------------
    {
        float4 mx = make_float4(NEGF, NEGF, NEGF, NEGF);
        float4 sm = make_float4(0.f, 0.f, 0.f, 0.f);
        #pragma unroll 8
        for (int t = 0; t < dl; t++) {
            const float4 v = *(const float4*)(wbase + (size_t)s_idx[TT + t] * DIM);
            mx.x = fmaxf(mx.x, v.x); mx.y = fmaxf(mx.y, v.y);
            mx.z = fmaxf(mx.z, v.z); mx.w = fmaxf(mx.w, v.w);
            sm.x += v.x; sm.y += v.y; sm.z += v.z; sm.w += v.w;
        }
        float4 av;
        if (dl > 0) {
            const float inv = 1.0f / (float)dl;
            av = make_float4(sm.x * inv, sm.y * inv, sm.z * inv, sm.w * inv);
        } else {
            mx = make_float4(0.f, 0.f, 0.f, 0.f);
            av = make_float4(0.f, 0.f, 0.f, 0.f);
        }
        *(float4*)(orow + DIM)     = mx;   // d_max  -> [512, 1024)
        *(float4*)(orow + 3 * DIM) = av;   // d_avg  -> [1536, 2048)
    }
}

extern "C" void kernel_launch(void* const* d_in, const int* in_sizes, int n_in,
                              void* d_out, int out_size)
{
    const void* title = d_in[0];
    const void* desc  = d_in[1];
    const void* tlen  = d_in[2];
    const void* dlen  = d_in[3];
    const float* w2v  = (const float*)d_in[n_in - 1];
    float* out        = (float*)d_out;

    const int B = in_sizes[2];   // t_len has B elements

    swem_cat_kernel<<<B, 128>>>(title, desc, tlen, dlen, w2v, out);
}